// round 5
// baseline (speedup 1.0000x reference)
#include <cuda_runtime.h>
#include <cuda_bf16.h>

// Problem constants (fixed by reference setup_inputs)
#define N_B      32
#define N_C      3
#define HW       4096      // 64*64
#define HW4      1024      // HW / 4
#define N_EMBD   896
#define INNER    128       // 896 / 7
#define N_LVL    7
#define N_CLS    1000
#define ROOT_OFF 768       // 6 * INNER

#define NBLK     40        // 8 classifier blocks + 32 mean blocks
#define NTHR     512
#define KCHUNK   125       // k per classifier block (8 * 125 = 1000)
#define NCLS_BLK 8

// Scratch (__device__ globals; allocations forbidden). Counters are monotonic
// (never reset) => correct on the correctness call and every graph replay.
__device__ float4 g_P[N_CLS];               // {A + cls_b, W0, W1, W2}
__device__ unsigned long long g_cls_ctr;    // +8  per launch (publishers)
__device__ unsigned long long g_mean_ctr;   // +32 per launch (gen derivation)

// ---------------------------------------------------------------------------
// One kernel, inverted sync (small side publishes, wide side consumes):
//  blocks 0..7   (cls):  hoisted cls_w/cls_b loads, emb_w collapse,
//                        publish g_P[k] = {A+cls_b, W0, W1, W2}, arrive, EXIT.
//  blocks 8..39  (mean): channel means of x[b] kept in SHARED, poll for this
//                        launch's 8 publisher arrivals, read P via L2, write
//                        own 1000 outputs out[b, :].
// ---------------------------------------------------------------------------
__global__ __launch_bounds__(NTHR) void k_all(
    const float* __restrict__ x,
    const float* __restrict__ emb_w,
    const float* __restrict__ emb_b,
    const float* __restrict__ cls_w,
    const float* __restrict__ cls_b,
    float* __restrict__ out)
{
    const int tid = threadIdx.x;
    const int blk = blockIdx.x;

    if (blk < NCLS_BLK) {
        // ======================= classifier (publisher) blocks ==============
        const int kx = blk;                            // 0..7
        const int t  = tid & 127;                      // k-lane (0..124 active)
        const int jq = tid >> 7;                       // j-quarter (0..3)
        const int k  = kx * KCHUNK + t;
        const bool kv = (t < KCHUNK);

        // Hoist all global loads (one DRAM round, MLP=33)
        float wreg[32];
        float cbreg = 0.f;
        if (kv) {
            const int jbase = jq * 32;
            #pragma unroll
            for (int jj = 0; jj < 32; jj++)
                wreg[jj] = __ldg(&cls_w[(jbase + jj) * N_CLS + k]);
            if (jq == 0) cbreg = __ldg(&cls_b[k]);
        }

        __shared__ float sw[4][INNER];                 // [bias, ws0, ws1, ws2][j]
        __shared__ float part[4][4][INNER];            // [jq][A/W0/W1/W2][t]

        if (tid < INNER) {
            float w0 = 0.f, w1 = 0.f, w2 = 0.f;
            #pragma unroll
            for (int l = 0; l < N_LVL; l++) {
                w0 += emb_w[(3 * l + 0) * N_EMBD + ROOT_OFF + tid];
                w1 += emb_w[(3 * l + 1) * N_EMBD + ROOT_OFF + tid];
                w2 += emb_w[(3 * l + 2) * N_EMBD + ROOT_OFF + tid];
            }
            sw[0][tid] = emb_b[ROOT_OFF + tid];
            sw[1][tid] = w0;  sw[2][tid] = w1;  sw[3][tid] = w2;
        }
        __syncthreads();

        float aA = 0.f, a0 = 0.f, a1 = 0.f, a2 = 0.f;
        if (kv) {
            const int jbase = jq * 32;
            #pragma unroll
            for (int jj = 0; jj < 32; jj++) {
                const float w = wreg[jj];
                aA = fmaf(sw[0][jbase + jj], w, aA);
                a0 = fmaf(sw[1][jbase + jj], w, a0);
                a1 = fmaf(sw[2][jbase + jj], w, a1);
                a2 = fmaf(sw[3][jbase + jj], w, a2);
            }
        }
        part[jq][0][t] = (jq == 0) ? aA + cbreg : aA;  // fold cls_b into A
        part[jq][1][t] = a0;
        part[jq][2][t] = a1;
        part[jq][3][t] = a2;
        __syncthreads();

        if (tid < KCHUNK) {
            g_P[kx * KCHUNK + tid] = make_float4(
                part[0][0][tid] + part[1][0][tid] + part[2][0][tid] + part[3][0][tid],
                part[0][1][tid] + part[1][1][tid] + part[2][1][tid] + part[3][1][tid],
                part[0][2][tid] + part[1][2][tid] + part[2][2][tid] + part[3][2][tid],
                part[0][3][tid] + part[1][3][tid] + part[2][3][tid] + part[3][3][tid]);
        }
        __syncthreads();
        if (tid == 0) {
            __threadfence();                           // release g_P
            atomicAdd(&g_cls_ctr, 1ULL);               // arrive
        }
        return;                                        // publishers exit
    }

    // ======================= mean (consumer) blocks =========================
    const int b = blk - NCLS_BLK;                      // batch 0..31
    const float4* xb = (const float4*)(x + (size_t)b * (N_C * HW));
    float s0, s1, s2;
    {
        float4 a0 = xb[0 * HW4 + tid], a1 = xb[0 * HW4 + 512 + tid];
        float4 b0 = xb[1 * HW4 + tid], b1 = xb[1 * HW4 + 512 + tid];
        float4 c0 = xb[2 * HW4 + tid], c1 = xb[2 * HW4 + 512 + tid];
        s0 = (a0.x + a0.y + a0.z + a0.w) + (a1.x + a1.y + a1.z + a1.w);
        s1 = (b0.x + b0.y + b0.z + b0.w) + (b1.x + b1.y + b1.z + b1.w);
        s2 = (c0.x + c0.y + c0.z + c0.w) + (c1.x + c1.y + c1.z + c1.w);
    }
    #pragma unroll
    for (int off = 16; off > 0; off >>= 1) {
        s0 += __shfl_xor_sync(0xFFFFFFFFu, s0, off);
        s1 += __shfl_xor_sync(0xFFFFFFFFu, s1, off);
        s2 += __shfl_xor_sync(0xFFFFFFFFu, s2, off);
    }
    __shared__ float wr[16][3];
    __shared__ float scoef[3];
    const int wid = tid >> 5, lane = tid & 31;
    if (lane == 0) { wr[wid][0] = s0; wr[wid][1] = s1; wr[wid][2] = s2; }
    __syncthreads();
    if (tid < 16) {
        float a0 = wr[tid][0], a1 = wr[tid][1], a2 = wr[tid][2];
        #pragma unroll
        for (int off = 8; off > 0; off >>= 1) {
            a0 += __shfl_xor_sync(0xFFFFu, a0, off);
            a1 += __shfl_xor_sync(0xFFFFu, a1, off);
            a2 += __shfl_xor_sync(0xFFFFu, a2, off);
        }
        if (tid == 0) {
            scoef[0] = a0 * (1.0f / HW);
            scoef[1] = a1 * (1.0f / HW);
            scoef[2] = a2 * (1.0f / HW);
            // Wait for THIS launch's 8 publisher arrivals. Generation from own
            // monotonic counter: mean arrivals in launch r occupy [32r, 32r+32).
            unsigned long long my = atomicAdd(&g_mean_ctr, 1ULL);
            unsigned long long target = (my / N_B + 1ULL) * NCLS_BLK;
            while (*(volatile unsigned long long*)&g_cls_ctr < target) { }
            __threadfence();                           // acquire g_P
        }
    }
    __syncthreads();

    const float c0 = scoef[0], c1 = scoef[1], c2 = scoef[2];
    float* ob = out + (size_t)b * N_CLS;
    #pragma unroll
    for (int i = tid; i < N_CLS; i += NTHR) {
        const float4 P = g_P[i];
        ob[i] = P.x + fmaf(c0, P.y, fmaf(c1, P.z, c2 * P.w));
    }
}

// ---------------------------------------------------------------------------
// Launch. Inputs (metadata order): x, emb_w, emb_b, cls_w, cls_b. Output f32.
// Graph-capturable: one kernel launch, no allocs, no syncs.
// ---------------------------------------------------------------------------
extern "C" void kernel_launch(void* const* d_in, const int* in_sizes, int n_in,
                              void* d_out, int out_size)
{
    const float* x     = (const float*)d_in[0];
    const float* emb_w = (const float*)d_in[1];
    const float* emb_b = (const float*)d_in[2];
    const float* cls_w = (const float*)d_in[3];
    const float* cls_b = (const float*)d_in[4];
    float* out = (float*)d_out;

    k_all<<<NBLK, NTHR>>>(x, emb_w, emb_b, cls_w, cls_b, out);
}

// round 6
// speedup vs baseline: 1.2000x; 1.2000x over previous
#include <cuda_runtime.h>
#include <cuda_bf16.h>

// Problem constants (fixed by reference setup_inputs)
#define N_B      32
#define N_C      3
#define HW       4096      // 64*64
#define HW4      1024      // HW / 4
#define N_EMBD   896
#define INNER    128       // 896 / 7
#define N_LVL    7
#define N_CLS    1000
#define ROOT_OFF 768       // 6 * INNER

#define NBLK     40        // 32 mean blocks + 8 classifier blocks
#define NTHR     512
#define KCHUNK   125       // k per classifier block (8 * 125 = 1000)
#define NCLS_BLK 8

// Scratch (__device__ globals; allocations forbidden). Counters are monotonic
// (never reset) => correct on the correctness call and every graph replay.
__device__ float g_coef[N_B * 4];           // per-batch channel means (float4 rows)
__device__ unsigned long long g_mean_ctr;   // +32 per launch (publisher arrivals)
__device__ unsigned long long g_cls_ctr;    // +8  per launch (generation derivation)

// ---------------------------------------------------------------------------
// One kernel (R4 dataflow, lightweight sync):
//  blocks 0..31  (mean): channel means -> g_coef (stcg), red.release arrive, EXIT
//  blocks 32..39 (cls):  gen atomic first (overlaps loads), hoisted cls_w/cls_b,
//                        emb_w collapse -> sP in shared, per-WARP acquire-poll
//                        for 32 arrivals, each warp writes its own 2 batches.
// ---------------------------------------------------------------------------
__global__ __launch_bounds__(NTHR) void k_all(
    const float* __restrict__ x,
    const float* __restrict__ emb_w,
    const float* __restrict__ emb_b,
    const float* __restrict__ cls_w,
    const float* __restrict__ cls_b,
    float* __restrict__ out)
{
    const int tid  = threadIdx.x;
    const int blk  = blockIdx.x;
    const int lane = tid & 31;

    if (blk < N_B) {
        // ======================= mean (publisher) blocks ====================
        const float4* xb = (const float4*)(x + (size_t)blk * (N_C * HW));
        float s0, s1, s2;
        {
            float4 a0 = xb[0 * HW4 + tid], a1 = xb[0 * HW4 + 512 + tid];
            float4 b0 = xb[1 * HW4 + tid], b1 = xb[1 * HW4 + 512 + tid];
            float4 c0 = xb[2 * HW4 + tid], c1 = xb[2 * HW4 + 512 + tid];
            s0 = (a0.x + a0.y + a0.z + a0.w) + (a1.x + a1.y + a1.z + a1.w);
            s1 = (b0.x + b0.y + b0.z + b0.w) + (b1.x + b1.y + b1.z + b1.w);
            s2 = (c0.x + c0.y + c0.z + c0.w) + (c1.x + c1.y + c1.z + c1.w);
        }
        #pragma unroll
        for (int off = 16; off > 0; off >>= 1) {
            s0 += __shfl_xor_sync(0xFFFFFFFFu, s0, off);
            s1 += __shfl_xor_sync(0xFFFFFFFFu, s1, off);
            s2 += __shfl_xor_sync(0xFFFFFFFFu, s2, off);
        }
        __shared__ float wr[16][3];
        const int wid = tid >> 5;
        if (lane == 0) { wr[wid][0] = s0; wr[wid][1] = s1; wr[wid][2] = s2; }
        __syncthreads();
        if (tid < 16) {
            float a0 = wr[tid][0], a1 = wr[tid][1], a2 = wr[tid][2];
            #pragma unroll
            for (int off = 8; off > 0; off >>= 1) {
                a0 += __shfl_xor_sync(0xFFFFu, a0, off);
                a1 += __shfl_xor_sync(0xFFFFu, a1, off);
                a2 += __shfl_xor_sync(0xFFFFu, a2, off);
            }
            if (tid == 0) {
                // One 128-bit L2-direct store, then release-arrive (no full fence)
                float4 cf = make_float4(a0 * (1.0f / HW), a1 * (1.0f / HW),
                                        a2 * (1.0f / HW), 0.0f);
                __stcg((float4*)&g_coef[blk * 4], cf);
                asm volatile("red.release.gpu.global.add.u64 [%0], %1;"
                             :: "l"(&g_mean_ctr), "l"(1ULL) : "memory");
            }
        }
        return;                                        // publishers exit
    }

    // ======================= classifier (consumer) blocks ===================
    const int kx = blk - N_B;                          // 0..7
    const int t  = tid & 127;                          // k-lane (0..124 active)
    const int jq = tid >> 7;                           // j-quarter (0..3)
    const int k  = kx * KCHUNK + t;
    const bool kv = (t < KCHUNK);

    __shared__ unsigned long long s_target;
    if (tid == 0) {
        // Generation from own monotonic counter; overlaps the loads below.
        unsigned long long my = atomicAdd(&g_cls_ctr, 1ULL);
        s_target = (my / NCLS_BLK + 1ULL) * N_B;
    }

    // Hoist all global loads (one DRAM round, MLP=33)
    float wreg[32];
    float cbreg = 0.f;
    if (kv) {
        const int jbase = jq * 32;
        #pragma unroll
        for (int jj = 0; jj < 32; jj++)
            wreg[jj] = __ldg(&cls_w[(jbase + jj) * N_CLS + k]);
        if (jq == 0) cbreg = __ldg(&cls_b[k]);
    }

    __shared__ float  sw[4][INNER];                    // [bias, ws0, ws1, ws2][j]
    __shared__ float  part[4][4][INNER];               // [jq][A/W0/W1/W2][t]
    __shared__ float4 sP[KCHUNK];                      // {A+cls_b, W0, W1, W2}

    if (tid < INNER) {
        float w0 = 0.f, w1 = 0.f, w2 = 0.f;
        #pragma unroll
        for (int l = 0; l < N_LVL; l++) {
            w0 += emb_w[(3 * l + 0) * N_EMBD + ROOT_OFF + tid];
            w1 += emb_w[(3 * l + 1) * N_EMBD + ROOT_OFF + tid];
            w2 += emb_w[(3 * l + 2) * N_EMBD + ROOT_OFF + tid];
        }
        sw[0][tid] = emb_b[ROOT_OFF + tid];
        sw[1][tid] = w0;  sw[2][tid] = w1;  sw[3][tid] = w2;
    }
    __syncthreads();

    float aA = 0.f, a0 = 0.f, a1 = 0.f, a2 = 0.f;
    if (kv) {
        const int jbase = jq * 32;
        #pragma unroll
        for (int jj = 0; jj < 32; jj++) {
            const float w = wreg[jj];
            aA = fmaf(sw[0][jbase + jj], w, aA);
            a0 = fmaf(sw[1][jbase + jj], w, a0);
            a1 = fmaf(sw[2][jbase + jj], w, a1);
            a2 = fmaf(sw[3][jbase + jj], w, a2);
        }
    }
    part[jq][0][t] = (jq == 0) ? aA + cbreg : aA;      // fold cls_b into A
    part[jq][1][t] = a0;
    part[jq][2][t] = a1;
    part[jq][3][t] = a2;
    __syncthreads();

    if (tid < KCHUNK) {
        sP[tid] = make_float4(
            part[0][0][tid] + part[1][0][tid] + part[2][0][tid] + part[3][0][tid],
            part[0][1][tid] + part[1][1][tid] + part[2][1][tid] + part[3][1][tid],
            part[0][2][tid] + part[1][2][tid] + part[2][2][tid] + part[3][2][tid],
            part[0][3][tid] + part[1][3][tid] + part[2][3][tid] + part[3][3][tid]);
    }
    __syncthreads();                                   // sP + s_target visible

    // Per-warp acquire-poll: lane 0 spins, warp proceeds independently.
    if (lane == 0) {
        const unsigned long long tgt = s_target;
        unsigned long long cur;
        do {
            asm volatile("ld.acquire.gpu.global.u64 %0, [%1];"
                         : "=l"(cur) : "l"(&g_mean_ctr) : "memory");
        } while (cur < tgt);
    }
    __syncwarp();

    // Warp w writes batches {2w, 2w+1}, k-range [kx*125, kx*125+125).
    const int wax = tid >> 5;
    #pragma unroll
    for (int q = 0; q < 2; q++) {
        const int b = wax * 2 + q;
        const float4 cf = __ldcg((const float4*)&g_coef[b * 4]);  // L2-fresh
        float* ob = out + (size_t)b * N_CLS + kx * KCHUNK;
        #pragma unroll
        for (int kk = 0; kk < 4; kk++) {
            const int kl = kk * 32 + lane;
            if (kl < KCHUNK) {
                const float4 P = sP[kl];
                ob[kl] = P.x + fmaf(cf.x, P.y, fmaf(cf.y, P.z, cf.z * P.w));
            }
        }
    }
}

// ---------------------------------------------------------------------------
// Launch. Inputs (metadata order): x, emb_w, emb_b, cls_w, cls_b. Output f32.
// Graph-capturable: one kernel launch, no allocs, no syncs.
// ---------------------------------------------------------------------------
extern "C" void kernel_launch(void* const* d_in, const int* in_sizes, int n_in,
                              void* d_out, int out_size)
{
    const float* x     = (const float*)d_in[0];
    const float* emb_w = (const float*)d_in[1];
    const float* emb_b = (const float*)d_in[2];
    const float* cls_w = (const float*)d_in[3];
    const float* cls_b = (const float*)d_in[4];
    float* out = (float*)d_out;

    k_all<<<NBLK, NTHR>>>(x, emb_w, emb_b, cls_w, cls_b, out);
}